// round 6
// baseline (speedup 1.0000x reference)
#include <cuda_runtime.h>
#include <math.h>

#define NB 16
#define NC 33
#define HIN 256
#define WIN 256
#define HF 128
#define WF 128
#define NFLOW 10
#define NPIX (HF * WF)                 // 16384
#define TPB 256
#define TILES 8
#define PIX_PER_BLOCK (NPIX / TILES)   // 2048
#define WARP_BLOCKS (NB * NFLOW * TILES) // 1280
#define SMOOTH_ELEMS (NB * NFLOW * HF * WF) // 2,621,440
#define SMOOTH_BLOCKS 2560
#define NCH (NB * NFLOW * 3)           // 480
#define RES_TOTAL (NB * NC * HF * WF)  // 8,650,752
#define RES_BLOCKS (RES_TOTAL / TPB)   // 33792
#define BLKS_PER_PLANE 64              // 16384 / 256
#define NREFPLANE (NB * 30)            // 480 ref planes
#define PSTRIDE 12                     // warp partials: 9 moments + pix (+pad)

// Scratch (device globals: allocation-free)
__device__ float  g_resized[RES_TOTAL];                    // ~34.6 MB
__device__ float  g_warp_part[WARP_BLOCKS * PSTRIDE];
__device__ float  g_smooth_part[SMOOTH_BLOCKS];
__device__ float2 g_ref_part[BLKS_PER_PLANE * NREFPLANE];  // [blk][plane] (S1,S11)
__device__ int    g_ctr;                                   // zero-initialized

__device__ __forceinline__ float charb(float d) {
    // (d^2 + EPS^2)^0.4, EPS = 1e-3
    return __powf(d * d + 1.0e-6f, 0.4f);
}

// ---------------------------------------------------------------------------
// Kernel 1: align-corners bilinear resize 256->128 + ref-plane moment partials
// (S1, S11) — free compute under the DRAM-bound stream.
// ---------------------------------------------------------------------------
__global__ __launch_bounds__(TPB) void resize_kernel(const float* __restrict__ img) {
    int idx = blockIdx.x * TPB + threadIdx.x;
    int x  = idx & (WF - 1);
    int y  = (idx >> 7) & (HF - 1);
    int bc = blockIdx.x >> 6;          // 64 blocks per plane

    const float s = (float)(255.0 / 127.0);
    float fy = (float)y * s;
    float fx = (float)x * s;
    int y0 = min(max((int)floorf(fy), 0), HIN - 2);
    int x0 = min(max((int)floorf(fx), 0), WIN - 2);
    float wy = fy - (float)y0;
    float wx = fx - (float)x0;

    const float* p = img + (size_t)bc * (HIN * WIN);
    float v00 = __ldg(p + y0 * WIN + x0);
    float v01 = __ldg(p + y0 * WIN + x0 + 1);
    float v10 = __ldg(p + (y0 + 1) * WIN + x0);
    float v11 = __ldg(p + (y0 + 1) * WIN + x0 + 1);

    float colL = v00 * (1.0f - wy) + v10 * wy;
    float colR = v01 * (1.0f - wy) + v11 * wy;
    float r = colL * (1.0f - wx) + colR * wx;
    g_resized[idx] = r;

    // Ref-plane moments: channels 0..29 of each batch are the SSIM/pixel "ref".
    int c33 = bc % NC;
    if (c33 < 30) {
        float s1 = r, s11 = r * r;
        int lane = threadIdx.x & 31;
        int wrp  = threadIdx.x >> 5;
        __shared__ float2 sm[8];
#pragma unroll
        for (int o = 16; o > 0; o >>= 1) {
            s1  += __shfl_down_sync(0xffffffffu, s1,  o);
            s11 += __shfl_down_sync(0xffffffffu, s11, o);
        }
        if (lane == 0) sm[wrp] = make_float2(s1, s11);
        __syncthreads();
        if (threadIdx.x == 0) {
            float a = 0.0f, b = 0.0f;
#pragma unroll
            for (int w = 0; w < 8; w++) { a += sm[w].x; b += sm[w].y; }
            int b_ = bc / NC;
            int plane = b_ * 30 + c33;
            int blk   = blockIdx.x & (BLKS_PER_PLANE - 1);
            g_ref_part[blk * NREFPLANE + plane] = make_float2(a, b);
        }
    }
}

// ---------------------------------------------------------------------------
// Kernel 2: smoothness gradients (flow-index axis + H axis), charbonnier.
// ---------------------------------------------------------------------------
__global__ __launch_bounds__(TPB) void smooth_kernel(const float* __restrict__ flows) {
    int base = blockIdx.x * (TPB * 4);
    float acc = 0.0f;
#pragma unroll
    for (int k = 0; k < 4; k++) {
        int e = base + k * TPB + threadIdx.x;
        int x  = e & (WF - 1);
        int y  = (e >> 7) & (HF - 1);
        int bi = e >> 14;
        int i  = bi % NFLOW;
        int b  = bi / NFLOW;
        const float* fb = flows + (size_t)b * 20 * NPIX;
        int px = y * WF + x;

#pragma unroll
        for (int comp = 0; comp < 2; comp++) {
            const float* ch = fb + (2 * i + comp) * NPIX;
            float gi;
            if (i == 0)
                gi = __ldg(fb + (2 + comp) * NPIX + px) - __ldg(ch + px);
            else if (i == NFLOW - 1)
                gi = __ldg(ch + px) - __ldg(fb + (2 * (NFLOW - 2) + comp) * NPIX + px);
            else
                gi = 0.5f * (__ldg(fb + (2 * (i + 1) + comp) * NPIX + px) -
                             __ldg(fb + (2 * (i - 1) + comp) * NPIX + px));
            float gh;
            if (y == 0)
                gh = __ldg(ch + WF + x) - __ldg(ch + px);
            else if (y == HF - 1)
                gh = __ldg(ch + px) - __ldg(ch + (HF - 2) * WF + x);
            else
                gh = 0.5f * (__ldg(ch + (y + 1) * WF + x) - __ldg(ch + (y - 1) * WF + x));

            acc += charb(gi) + charb(gh);
        }
    }

    __shared__ float sm[8];
    int lane = threadIdx.x & 31;
    int wrp  = threadIdx.x >> 5;
#pragma unroll
    for (int o = 16; o > 0; o >>= 1) acc += __shfl_down_sync(0xffffffffu, acc, o);
    if (lane == 0) sm[wrp] = acc;
    __syncthreads();
    if (threadIdx.x == 0) {
        float s = 0.0f;
#pragma unroll
        for (int w = 0; w < 8; w++) s += sm[w];
        g_smooth_part[blockIdx.x] = s;
    }
}

// ---------------------------------------------------------------------------
// Kernel 3: bilinear warp + warped-side moments (S2, S22, S12) + pixel charb;
// last block finalizes everything. Only 10 accumulators -> lower reg pressure.
// ---------------------------------------------------------------------------
__global__ __launch_bounds__(TPB, 6) void warp_kernel(const float* __restrict__ flows,
                                                      float* __restrict__ out) {
    int bidx = blockIdx.x;
    int tile = bidx & (TILES - 1);
    int bf   = bidx >> 3;            // TILES == 8
    int b = bf / NFLOW;
    int f = bf % NFLOW;
    int tid = threadIdx.x;

    const float* fxp = flows + (size_t)(b * 20 + 2 * f) * NPIX;
    const float* fyp = fxp + NPIX;
    const float* srcbase = g_resized + (size_t)(b * NC + 3 + f * 3) * NPIX;
    const float* refbase = g_resized + (size_t)(b * NC + f * 3) * NPIX;

    float acc[10];
#pragma unroll
    for (int i = 0; i < 10; i++) acc[i] = 0.0f;

    int p0 = tile * PIX_PER_BLOCK;
#pragma unroll
    for (int k = 0; k < PIX_PER_BLOCK; k += TPB) {
        int p = p0 + k + tid;
        int x = p & (WF - 1);
        int y = p >> 7;

        float gx = (float)x + __ldg(fxp + p);
        float gy = (float)y + __ldg(fyp + p);
        float x0f = floorf(gx);
        float y0f = floorf(gy);
        float wx = gx - x0f;
        float wy = gy - y0f;
        int ix0 = min(max((int)x0f, 0), WF - 1);
        int iy0 = min(max((int)y0f, 0), HF - 1);
        int ix1 = min(ix0 + 1, WF - 1);
        int iy1 = min(iy0 + 1, HF - 1);

        int o00 = iy0 * WF + ix0;
        int o01 = iy0 * WF + ix1;
        int o10 = iy1 * WF + ix0;
        int o11 = iy1 * WF + ix1;

#pragma unroll
        for (int c = 0; c < 3; c++) {
            const float* sp = srcbase + c * NPIX;
            float v00 = __ldg(sp + o00);
            float v01 = __ldg(sp + o01);
            float v10 = __ldg(sp + o10);
            float v11 = __ldg(sp + o11);
            float top = v00 * (1.0f - wx) + v01 * wx;
            float bot = v10 * (1.0f - wx) + v11 * wx;
            float w   = top * (1.0f - wy) + bot * wy;
            float r   = __ldg(refbase + c * NPIX + p);

            acc[c * 3 + 0] += w;
            acc[c * 3 + 1] += w * w;
            acc[c * 3 + 2] += r * w;
            acc[9] += charb(r - w);
        }
    }

    __shared__ float sm[8 * 10];
    int lane = tid & 31;
    int wrp  = tid >> 5;
#pragma unroll
    for (int i = 0; i < 10; i++) {
        float v = acc[i];
#pragma unroll
        for (int o = 16; o > 0; o >>= 1) v += __shfl_down_sync(0xffffffffu, v, o);
        if (lane == 0) sm[wrp * 10 + i] = v;
    }
    __syncthreads();
    if (tid < 10) {
        float s = 0.0f;
#pragma unroll
        for (int w = 0; w < 8; w++) s += sm[w * 10 + tid];
        g_warp_part[bidx * PSTRIDE + tid] = s;
    }

    // ---- last-block finalization ----
    __shared__ bool is_last;
    __threadfence();
    __syncthreads();
    if (tid == 0) {
        int old = atomicAdd(&g_ctr, 1);
        is_last = (old == WARP_BLOCKS - 1);
    }
    __syncthreads();
    if (!is_last) return;
    __threadfence();

    __shared__ float  smom[NCH * 3];     // warped moments per (bf,c)
    __shared__ float2 sref[NREFPLANE];   // (S1, S11) per ref plane

    // Warped-side moments: sum 8 tile partials.
    for (int t = tid; t < NCH * 3; t += TPB) {
        int bfc = t / 3;
        int m   = t % 3;
        int bfi = bfc / 3;
        int c   = bfc % 3;
        const float* pp = g_warp_part + (size_t)(bfi * TILES) * PSTRIDE + c * 3 + m;
        float s = 0.0f;
#pragma unroll
        for (int tl = 0; tl < TILES; tl++) s += pp[tl * PSTRIDE];
        smom[t] = s;
    }

    // Ref-side moments: 64 coalesced rows of 480 float2.
    for (int pl = tid; pl < NREFPLANE; pl += TPB) {
        float a = 0.0f, bb = 0.0f;
#pragma unroll
        for (int j = 0; j < BLKS_PER_PLANE; j++) {
            float2 v = g_ref_part[j * NREFPLANE + pl];
            a += v.x; bb += v.y;
        }
        sref[pl] = make_float2(a, bb);
    }

    float pix_s = 0.0f, sm_s = 0.0f;
    for (int i = tid; i < WARP_BLOCKS; i += TPB)
        pix_s += g_warp_part[i * PSTRIDE + 9];
    for (int i = tid; i < SMOOTH_BLOCKS; i += TPB)
        sm_s += g_smooth_part[i];
    __syncthreads();

    // Per-channel SSIM in f32.
    float ssim_s = 0.0f;
    for (int ch = tid; ch < NCH; ch += TPB) {
        int bfi = ch / 3, c = ch % 3;
        int b_ = bfi / NFLOW, f_ = bfi % NFLOW;
        float2 rm = sref[b_ * 30 + f_ * 3 + c];
        float S1 = rm.x, S11 = rm.y;
        const float* m = smom + ch * 3;
        float S2 = m[0], S22 = m[1], S12 = m[2];
        const float invN   = 1.0f / (float)NPIX;
        const float invNm1 = 1.0f / (float)(NPIX - 1);
        float mu1 = S1 * invN, mu2 = S2 * invN;
        float var1 = (S11 - S1 * S1 * invN) * invNm1;
        float var2 = (S22 - S2 * S2 * invN) * invNm1;
        float s12  = (S12 - S1 * S2 * invN) * invN;
        float num = (2.0f * mu1 * mu2 + 1.0e-4f) * (2.0f * s12 + 1.0e-3f);
        float den = (mu1 * mu1 + mu2 * mu2 + 1.0e-4f) * (var1 + var2 + 1.0e-3f);
        ssim_s += num / den;
    }

    __shared__ float sred[3 * 8];
#pragma unroll
    for (int o = 16; o > 0; o >>= 1) {
        ssim_s += __shfl_down_sync(0xffffffffu, ssim_s, o);
        pix_s  += __shfl_down_sync(0xffffffffu, pix_s,  o);
        sm_s   += __shfl_down_sync(0xffffffffu, sm_s,   o);
    }
    if (lane == 0) {
        sred[wrp * 3 + 0] = ssim_s;
        sred[wrp * 3 + 1] = pix_s;
        sred[wrp * 3 + 2] = sm_s;
    }
    __syncthreads();
    if (tid == 0) {
        float a = 0.0f, bb = 0.0f, cc = 0.0f;
#pragma unroll
        for (int w = 0; w < 8; w++) {
            a  += sred[w * 3 + 0];
            bb += sred[w * 3 + 1];
            cc += sred[w * 3 + 2];
        }
        out[0] = bb * (1.0f / (float)(NB * NFLOW * 3 * NPIX))   // pixel (w=1.0)
               + 0.01f * cc * (1.0f / (float)SMOOTH_ELEMS)      // smooth (w=0.01)
               + a * (1.0f / (float)NCH);                       // ssim (w=1.0)
        g_ctr = 0;  // reset for next graph replay
    }
}

extern "C" void kernel_launch(void* const* d_in, const int* in_sizes, int n_in,
                              void* d_out, int out_size) {
    const float* images = (const float*)d_in[0];  // (16,33,256,256) f32
    const float* flows  = (const float*)d_in[1];  // (16,20,128,128) f32
    (void)in_sizes; (void)n_in; (void)out_size;

    resize_kernel<<<RES_BLOCKS, TPB>>>(images);
    smooth_kernel<<<SMOOTH_BLOCKS, TPB>>>(flows);
    warp_kernel<<<WARP_BLOCKS, TPB>>>(flows, (float*)d_out);
}

// round 7
// speedup vs baseline: 1.1420x; 1.1420x over previous
#include <cuda_runtime.h>
#include <math.h>

#define NB 16
#define NC 33
#define HIN 256
#define WIN 256
#define HF 128
#define WF 128
#define NFLOW 10
#define NPIX (HF * WF)                 // 16384
#define TPB 256
#define TILES 8
#define PIX_PER_BLOCK (NPIX / TILES)   // 2048
#define WARP_BLOCKS (NB * NFLOW * TILES) // 1280
#define SMOOTH_ELEMS (NB * NFLOW * HF * WF) // 2,621,440
#define SMOOTH_BLOCKS 2560
#define NCH (NB * NFLOW * 3)           // 480
#define RES_TOTAL (NB * NC * HF * WF)  // 8,650,752
#define RES_BLOCKS (RES_TOTAL / TPB)   // 33792

// Scratch (device globals: allocation-free)
__device__ float g_resized[RES_TOTAL];             // ~34.6 MB
__device__ float g_warp_part[WARP_BLOCKS * 16];    // 3ch x 5 moments + pixel charb
__device__ float g_smooth_part[SMOOTH_BLOCKS];
__device__ int   g_ctr;                            // zero-initialized

__device__ __forceinline__ float charb(float d) {
    // (d^2 + EPS^2)^0.4, EPS = 1e-3
    return __powf(d * d + 1.0e-6f, 0.4f);
}

// ---------------------------------------------------------------------------
// Kernel 1: align-corners bilinear resize 256x256 -> 128x128 (lean, R3 form)
// ---------------------------------------------------------------------------
__global__ __launch_bounds__(TPB) void resize_kernel(const float* __restrict__ img) {
    int idx = blockIdx.x * TPB + threadIdx.x;
    int x  = idx & (WF - 1);
    int y  = (idx >> 7) & (HF - 1);
    int bc = idx >> 14;

    const float s = (float)(255.0 / 127.0);
    float fy = (float)y * s;
    float fx = (float)x * s;
    int y0 = min(max((int)floorf(fy), 0), HIN - 2);
    int x0 = min(max((int)floorf(fx), 0), WIN - 2);
    float wy = fy - (float)y0;
    float wx = fx - (float)x0;

    const float* p = img + (size_t)bc * (HIN * WIN);
    float v00 = __ldg(p + y0 * WIN + x0);
    float v01 = __ldg(p + y0 * WIN + x0 + 1);
    float v10 = __ldg(p + (y0 + 1) * WIN + x0);
    float v11 = __ldg(p + (y0 + 1) * WIN + x0 + 1);

    float colL = v00 * (1.0f - wy) + v10 * wy;
    float colR = v01 * (1.0f - wy) + v11 * wy;
    g_resized[idx] = colL * (1.0f - wx) + colR * wx;
}

// ---------------------------------------------------------------------------
// Kernel 2: smoothness gradients (flow-index axis + H axis), charbonnier.
// ---------------------------------------------------------------------------
__global__ __launch_bounds__(TPB) void smooth_kernel(const float* __restrict__ flows) {
    int base = blockIdx.x * (TPB * 4);
    float acc = 0.0f;
#pragma unroll
    for (int k = 0; k < 4; k++) {
        int e = base + k * TPB + threadIdx.x;
        int x  = e & (WF - 1);
        int y  = (e >> 7) & (HF - 1);
        int bi = e >> 14;
        int i  = bi % NFLOW;
        int b  = bi / NFLOW;
        const float* fb = flows + (size_t)b * 20 * NPIX;
        int px = y * WF + x;

#pragma unroll
        for (int comp = 0; comp < 2; comp++) {
            const float* ch = fb + (2 * i + comp) * NPIX;
            float gi;
            if (i == 0)
                gi = __ldg(fb + (2 + comp) * NPIX + px) - __ldg(ch + px);
            else if (i == NFLOW - 1)
                gi = __ldg(ch + px) - __ldg(fb + (2 * (NFLOW - 2) + comp) * NPIX + px);
            else
                gi = 0.5f * (__ldg(fb + (2 * (i + 1) + comp) * NPIX + px) -
                             __ldg(fb + (2 * (i - 1) + comp) * NPIX + px));
            float gh;
            if (y == 0)
                gh = __ldg(ch + WF + x) - __ldg(ch + px);
            else if (y == HF - 1)
                gh = __ldg(ch + px) - __ldg(ch + (HF - 2) * WF + x);
            else
                gh = 0.5f * (__ldg(ch + (y + 1) * WF + x) - __ldg(ch + (y - 1) * WF + x));

            acc += charb(gi) + charb(gh);
        }
    }

    __shared__ float sm[8];
    int lane = threadIdx.x & 31;
    int wrp  = threadIdx.x >> 5;
#pragma unroll
    for (int o = 16; o > 0; o >>= 1) acc += __shfl_down_sync(0xffffffffu, acc, o);
    if (lane == 0) sm[wrp] = acc;
    __syncthreads();
    if (threadIdx.x == 0) {
        float s = 0.0f;
#pragma unroll
        for (int w = 0; w < 8; w++) s += sm[w];
        g_smooth_part[blockIdx.x] = s;
    }
}

// ---------------------------------------------------------------------------
// Kernel 3: bilinear warp + SSIM moments + pixel charbonnier (proven 33.9us
// form from R5: natural register allocation, 16 accumulators, last-block
// finalization).
// ---------------------------------------------------------------------------
__global__ __launch_bounds__(TPB) void warp_kernel(const float* __restrict__ flows,
                                                   float* __restrict__ out) {
    int bidx = blockIdx.x;
    int tile = bidx & (TILES - 1);
    int bf   = bidx >> 3;            // TILES == 8
    int b = bf / NFLOW;
    int f = bf % NFLOW;
    int tid = threadIdx.x;

    const float* fxp = flows + (size_t)(b * 20 + 2 * f) * NPIX;
    const float* fyp = fxp + NPIX;
    const float* srcbase = g_resized + (size_t)(b * NC + 3 + f * 3) * NPIX;
    const float* refbase = g_resized + (size_t)(b * NC + f * 3) * NPIX;

    float acc[16];
#pragma unroll
    for (int i = 0; i < 16; i++) acc[i] = 0.0f;

    int p0 = tile * PIX_PER_BLOCK;
#pragma unroll
    for (int k = 0; k < PIX_PER_BLOCK; k += TPB) {
        int p = p0 + k + tid;
        int x = p & (WF - 1);
        int y = p >> 7;

        float gx = (float)x + __ldg(fxp + p);
        float gy = (float)y + __ldg(fyp + p);
        float x0f = floorf(gx);
        float y0f = floorf(gy);
        float wx = gx - x0f;
        float wy = gy - y0f;
        int ix0 = min(max((int)x0f, 0), WF - 1);
        int iy0 = min(max((int)y0f, 0), HF - 1);
        int ix1 = min(ix0 + 1, WF - 1);
        int iy1 = min(iy0 + 1, HF - 1);

        int o00 = iy0 * WF + ix0;
        int o01 = iy0 * WF + ix1;
        int o10 = iy1 * WF + ix0;
        int o11 = iy1 * WF + ix1;

#pragma unroll
        for (int c = 0; c < 3; c++) {
            const float* sp = srcbase + c * NPIX;
            float v00 = __ldg(sp + o00);
            float v01 = __ldg(sp + o01);
            float v10 = __ldg(sp + o10);
            float v11 = __ldg(sp + o11);
            float top = v00 * (1.0f - wx) + v01 * wx;
            float bot = v10 * (1.0f - wx) + v11 * wx;
            float w   = top * (1.0f - wy) + bot * wy;
            float r   = __ldg(refbase + c * NPIX + p);

            acc[c * 5 + 0] += r;
            acc[c * 5 + 1] += w;
            acc[c * 5 + 2] += r * r;
            acc[c * 5 + 3] += w * w;
            acc[c * 5 + 4] += r * w;
            acc[15] += charb(r - w);
        }
    }

    __shared__ float sm[8 * 16];
    int lane = tid & 31;
    int wrp  = tid >> 5;
#pragma unroll
    for (int i = 0; i < 16; i++) {
        float v = acc[i];
#pragma unroll
        for (int o = 16; o > 0; o >>= 1) v += __shfl_down_sync(0xffffffffu, v, o);
        if (lane == 0) sm[wrp * 16 + i] = v;
    }
    __syncthreads();
    if (tid < 16) {
        float s = 0.0f;
#pragma unroll
        for (int w = 0; w < 8; w++) s += sm[w * 16 + tid];
        g_warp_part[bidx * 16 + tid] = s;
    }

    // ---- last-block finalization ----
    __shared__ bool is_last;
    __threadfence();
    __syncthreads();
    if (tid == 0) {
        int old = atomicAdd(&g_ctr, 1);
        is_last = (old == WARP_BLOCKS - 1);
    }
    __syncthreads();
    if (!is_last) return;
    __threadfence();

    __shared__ float smom[NCH * 5];   // 2400 floats
    for (int t = tid; t < NCH * 5; t += TPB) {
        int bfc = t / 5;
        int m   = t % 5;
        int bfi = bfc / 3;
        int c   = bfc % 3;
        const float* pp = g_warp_part + (size_t)(bfi * TILES) * 16 + c * 5 + m;
        float s = 0.0f;
#pragma unroll
        for (int tl = 0; tl < TILES; tl++) s += pp[tl * 16];
        smom[t] = s;
    }

    float pix_s = 0.0f, sm_s = 0.0f;
    for (int i = tid; i < WARP_BLOCKS; i += TPB)
        pix_s += g_warp_part[i * 16 + 15];
    for (int i = tid; i < SMOOTH_BLOCKS; i += TPB)
        sm_s += g_smooth_part[i];
    __syncthreads();

    float ssim_s = 0.0f;
    for (int ch = tid; ch < NCH; ch += TPB) {
        const float* m = smom + ch * 5;
        float S1 = m[0], S2 = m[1], S11 = m[2], S22 = m[3], S12 = m[4];
        const float invN   = 1.0f / (float)NPIX;
        const float invNm1 = 1.0f / (float)(NPIX - 1);
        float mu1 = S1 * invN, mu2 = S2 * invN;
        float var1 = (S11 - S1 * S1 * invN) * invNm1;
        float var2 = (S22 - S2 * S2 * invN) * invNm1;
        float s12  = (S12 - S1 * S2 * invN) * invN;
        float num = (2.0f * mu1 * mu2 + 1.0e-4f) * (2.0f * s12 + 1.0e-3f);
        float den = (mu1 * mu1 + mu2 * mu2 + 1.0e-4f) * (var1 + var2 + 1.0e-3f);
        ssim_s += num / den;
    }

    __shared__ float sred[3 * 8];
#pragma unroll
    for (int o = 16; o > 0; o >>= 1) {
        ssim_s += __shfl_down_sync(0xffffffffu, ssim_s, o);
        pix_s  += __shfl_down_sync(0xffffffffu, pix_s,  o);
        sm_s   += __shfl_down_sync(0xffffffffu, sm_s,   o);
    }
    if (lane == 0) {
        sred[wrp * 3 + 0] = ssim_s;
        sred[wrp * 3 + 1] = pix_s;
        sred[wrp * 3 + 2] = sm_s;
    }
    __syncthreads();
    if (tid == 0) {
        float a = 0.0f, bb = 0.0f, cc = 0.0f;
#pragma unroll
        for (int w = 0; w < 8; w++) {
            a  += sred[w * 3 + 0];
            bb += sred[w * 3 + 1];
            cc += sred[w * 3 + 2];
        }
        out[0] = bb * (1.0f / (float)(NB * NFLOW * 3 * NPIX))   // pixel (w=1.0)
               + 0.01f * cc * (1.0f / (float)SMOOTH_ELEMS)      // smooth (w=0.01)
               + a * (1.0f / (float)NCH);                       // ssim (w=1.0)
        g_ctr = 0;  // reset for next graph replay
    }
}

extern "C" void kernel_launch(void* const* d_in, const int* in_sizes, int n_in,
                              void* d_out, int out_size) {
    const float* images = (const float*)d_in[0];  // (16,33,256,256) f32
    const float* flows  = (const float*)d_in[1];  // (16,20,128,128) f32
    (void)in_sizes; (void)n_in; (void)out_size;

    resize_kernel<<<RES_BLOCKS, TPB>>>(images);
    smooth_kernel<<<SMOOTH_BLOCKS, TPB>>>(flows);
    warp_kernel<<<WARP_BLOCKS, TPB>>>(flows, (float*)d_out);
}

// round 10
// speedup vs baseline: 1.2334x; 1.0800x over previous
#include <cuda_runtime.h>
#include <math.h>

#define NB 16
#define NC 33
#define HIN 256
#define WIN 256
#define HF 128
#define WF 128
#define NFLOW 10
#define NPIX (HF * WF)                 // 16384
#define TPB 256
#define TILES 16
#define PIX_PER_BLOCK (NPIX / TILES)   // 1024
#define WARP_BLOCKS (NB * NFLOW * TILES) // 2560
#define SMOOTH_ELEMS (NB * NFLOW * HF * WF) // 2,621,440
#define SMOOTH_BLOCKS ((NB * NPIX) / TPB)  // 1024 (one thread per (b,pixel))
#define NCH (NB * NFLOW * 3)           // 480
#define RES_TOTAL (NB * NC * HF * WF)  // 8,650,752
#define RES_BLOCKS (RES_TOTAL / TPB)   // 33792

// Scratch (device globals: allocation-free)
__device__ float g_resized[RES_TOTAL];             // ~34.6 MB
__device__ float g_warp_part[WARP_BLOCKS * 16];    // 3ch x 5 moments + pixel charb
__device__ float g_smooth_part[SMOOTH_BLOCKS];
__device__ int   g_ctr;                            // zero-initialized

__device__ __forceinline__ float charb(float d) {
    // (d^2 + EPS^2)^0.4, EPS = 1e-3
    return __powf(d * d + 1.0e-6f, 0.4f);
}

// ---------------------------------------------------------------------------
// Kernel 1: align-corners bilinear resize 256x256 -> 128x128 (lean, proven)
// ---------------------------------------------------------------------------
__global__ __launch_bounds__(TPB) void resize_kernel(const float* __restrict__ img) {
    int idx = blockIdx.x * TPB + threadIdx.x;
    int x  = idx & (WF - 1);
    int y  = (idx >> 7) & (HF - 1);
    int bc = idx >> 14;

    const float s = (float)(255.0 / 127.0);
    float fy = (float)y * s;
    float fx = (float)x * s;
    int y0 = min(max((int)floorf(fy), 0), HIN - 2);
    int x0 = min(max((int)floorf(fx), 0), WIN - 2);
    float wy = fy - (float)y0;
    float wx = fx - (float)x0;

    const float* p = img + (size_t)bc * (HIN * WIN);
    float v00 = __ldg(p + y0 * WIN + x0);
    float v01 = __ldg(p + y0 * WIN + x0 + 1);
    float v10 = __ldg(p + (y0 + 1) * WIN + x0);
    float v11 = __ldg(p + (y0 + 1) * WIN + x0 + 1);

    float colL = v00 * (1.0f - wy) + v10 * wy;
    float colR = v01 * (1.0f - wy) + v11 * wy;
    g_resized[idx] = colL * (1.0f - wx) + colR * wx;
}

// ---------------------------------------------------------------------------
// Kernel 2: smoothness via sliding window over the flow index.
// One thread owns (b, pixel); index-gradient neighbors live in registers.
// ---------------------------------------------------------------------------
__global__ __launch_bounds__(TPB) void smooth_kernel(const float* __restrict__ flows) {
    int t  = blockIdx.x * TPB + threadIdx.x;   // 262144 threads
    int b  = t >> 14;
    int px = t & (NPIX - 1);
    int y  = px >> 7;
    int x  = px & (WF - 1);
    const float* fb = flows + (size_t)b * 20 * NPIX;

    float acc = 0.0f;
#pragma unroll
    for (int comp = 0; comp < 2; comp++) {
        float vp = 0.0f;
        float vc = __ldg(fb + comp * NPIX + px);         // i = 0
        float vn = __ldg(fb + (2 + comp) * NPIX + px);   // i = 1
#pragma unroll
        for (int i = 0; i < NFLOW; i++) {
            float gi = (i == 0)        ? (vn - vc)
                     : (i == NFLOW - 1) ? (vc - vp)
                                        : 0.5f * (vn - vp);
            const float* ch = fb + (2 * i + comp) * NPIX;
            float gh;
            if (y == 0)
                gh = __ldg(ch + WF + x) - vc;
            else if (y == HF - 1)
                gh = vc - __ldg(ch + (HF - 2) * WF + x);
            else
                gh = 0.5f * (__ldg(ch + (y + 1) * WF + x) - __ldg(ch + (y - 1) * WF + x));

            acc += charb(gi) + charb(gh);

            vp = vc; vc = vn;
            if (i < NFLOW - 2) vn = __ldg(fb + (2 * (i + 2) + comp) * NPIX + px);
        }
    }

    __shared__ float sm[8];
    int lane = threadIdx.x & 31;
    int wrp  = threadIdx.x >> 5;
#pragma unroll
    for (int o = 16; o > 0; o >>= 1) acc += __shfl_down_sync(0xffffffffu, acc, o);
    if (lane == 0) sm[wrp] = acc;
    __syncthreads();
    if (threadIdx.x == 0) {
        float s = 0.0f;
#pragma unroll
        for (int w = 0; w < 8; w++) s += sm[w];
        g_smooth_part[blockIdx.x] = s;
    }
}

// ---------------------------------------------------------------------------
// Kernel 3: bilinear warp + SSIM moments + pixel charbonnier.
// TILES=16 for better wave balance; flow prefetch across iterations.
// Last block finalizes everything.
// ---------------------------------------------------------------------------
__global__ __launch_bounds__(TPB) void warp_kernel(const float* __restrict__ flows,
                                                   float* __restrict__ out) {
    int bidx = blockIdx.x;
    int tile = bidx & (TILES - 1);
    int bf   = bidx >> 4;            // TILES == 16
    int b = bf / NFLOW;
    int f = bf % NFLOW;
    int tid = threadIdx.x;

    const float* fxp = flows + (size_t)(b * 20 + 2 * f) * NPIX;
    const float* fyp = fxp + NPIX;
    const float* srcbase = g_resized + (size_t)(b * NC + 3 + f * 3) * NPIX;
    const float* refbase = g_resized + (size_t)(b * NC + f * 3) * NPIX;

    float acc[16];
#pragma unroll
    for (int i = 0; i < 16; i++) acc[i] = 0.0f;

    int p0 = tile * PIX_PER_BLOCK;
    float flx = __ldg(fxp + p0 + tid);
    float fly = __ldg(fyp + p0 + tid);
#pragma unroll
    for (int k = 0; k < PIX_PER_BLOCK; k += TPB) {
        int p = p0 + k + tid;
        float nflx = 0.0f, nfly = 0.0f;
        if (k + TPB < PIX_PER_BLOCK) {      // prefetch next iteration's flow
            nflx = __ldg(fxp + p + TPB);
            nfly = __ldg(fyp + p + TPB);
        }
        int x = p & (WF - 1);
        int y = p >> 7;

        float gx = (float)x + flx;
        float gy = (float)y + fly;
        float x0f = floorf(gx);
        float y0f = floorf(gy);
        float wx = gx - x0f;
        float wy = gy - y0f;
        int ix0 = min(max((int)x0f, 0), WF - 1);
        int iy0 = min(max((int)y0f, 0), HF - 1);
        int ix1 = min(ix0 + 1, WF - 1);
        int iy1 = min(iy0 + 1, HF - 1);

        int o00 = iy0 * WF + ix0;
        int o01 = iy0 * WF + ix1;
        int o10 = iy1 * WF + ix0;
        int o11 = iy1 * WF + ix1;

#pragma unroll
        for (int c = 0; c < 3; c++) {
            const float* sp = srcbase + c * NPIX;
            float v00 = __ldg(sp + o00);
            float v01 = __ldg(sp + o01);
            float v10 = __ldg(sp + o10);
            float v11 = __ldg(sp + o11);
            float top = v00 * (1.0f - wx) + v01 * wx;
            float bot = v10 * (1.0f - wx) + v11 * wx;
            float w   = top * (1.0f - wy) + bot * wy;
            float r   = __ldg(refbase + c * NPIX + p);

            acc[c * 5 + 0] += r;
            acc[c * 5 + 1] += w;
            acc[c * 5 + 2] += r * r;
            acc[c * 5 + 3] += w * w;
            acc[c * 5 + 4] += r * w;
            acc[15] += charb(r - w);
        }
        flx = nflx; fly = nfly;
    }

    __shared__ float sm[8 * 16];
    int lane = tid & 31;
    int wrp  = tid >> 5;
#pragma unroll
    for (int i = 0; i < 16; i++) {
        float v = acc[i];
#pragma unroll
        for (int o = 16; o > 0; o >>= 1) v += __shfl_down_sync(0xffffffffu, v, o);
        if (lane == 0) sm[wrp * 16 + i] = v;
    }
    __syncthreads();
    if (tid < 16) {
        float s = 0.0f;
#pragma unroll
        for (int w = 0; w < 8; w++) s += sm[w * 16 + tid];
        g_warp_part[bidx * 16 + tid] = s;
    }

    // ---- last-block finalization ----
    __shared__ bool is_last;
    __threadfence();
    __syncthreads();
    if (tid == 0) {
        int old = atomicAdd(&g_ctr, 1);
        is_last = (old == WARP_BLOCKS - 1);
    }
    __syncthreads();
    if (!is_last) return;
    __threadfence();

    __shared__ float smom[NCH * 5];   // 2400 floats
    for (int t = tid; t < NCH * 5; t += TPB) {
        int bfc = t / 5;
        int m   = t % 5;
        int bfi = bfc / 3;
        int c   = bfc % 3;
        const float* pp = g_warp_part + (size_t)(bfi * TILES) * 16 + c * 5 + m;
        float s = 0.0f;
#pragma unroll
        for (int tl = 0; tl < TILES; tl++) s += pp[tl * 16];
        smom[t] = s;
    }

    float pix_s = 0.0f, sm_s = 0.0f;
    for (int i = tid; i < WARP_BLOCKS; i += TPB)
        pix_s += g_warp_part[i * 16 + 15];
    for (int i = tid; i < SMOOTH_BLOCKS; i += TPB)
        sm_s += g_smooth_part[i];
    __syncthreads();

    float ssim_s = 0.0f;
    for (int ch = tid; ch < NCH; ch += TPB) {
        const float* m = smom + ch * 5;
        float S1 = m[0], S2 = m[1], S11 = m[2], S22 = m[3], S12 = m[4];
        const float invN   = 1.0f / (float)NPIX;
        const float invNm1 = 1.0f / (float)(NPIX - 1);
        float mu1 = S1 * invN, mu2 = S2 * invN;
        float var1 = (S11 - S1 * S1 * invN) * invNm1;
        float var2 = (S22 - S2 * S2 * invN) * invNm1;
        float s12  = (S12 - S1 * S2 * invN) * invN;
        float num = (2.0f * mu1 * mu2 + 1.0e-4f) * (2.0f * s12 + 1.0e-3f);
        float den = (mu1 * mu1 + mu2 * mu2 + 1.0e-4f) * (var1 + var2 + 1.0e-3f);
        ssim_s += num / den;
    }

    __shared__ float sred[3 * 8];
#pragma unroll
    for (int o = 16; o > 0; o >>= 1) {
        ssim_s += __shfl_down_sync(0xffffffffu, ssim_s, o);
        pix_s  += __shfl_down_sync(0xffffffffu, pix_s,  o);
        sm_s   += __shfl_down_sync(0xffffffffu, sm_s,   o);
    }
    if (lane == 0) {
        sred[wrp * 3 + 0] = ssim_s;
        sred[wrp * 3 + 1] = pix_s;
        sred[wrp * 3 + 2] = sm_s;
    }
    __syncthreads();
    if (tid == 0) {
        float a = 0.0f, bb = 0.0f, cc = 0.0f;
#pragma unroll
        for (int w = 0; w < 8; w++) {
            a  += sred[w * 3 + 0];
            bb += sred[w * 3 + 1];
            cc += sred[w * 3 + 2];
        }
        out[0] = bb * (1.0f / (float)(NB * NFLOW * 3 * NPIX))   // pixel (w=1.0)
               + 0.01f * cc * (1.0f / (float)SMOOTH_ELEMS)      // smooth (w=0.01)
               + a * (1.0f / (float)NCH);                       // ssim (w=1.0)
        g_ctr = 0;  // reset for next graph replay
    }
}

extern "C" void kernel_launch(void* const* d_in, const int* in_sizes, int n_in,
                              void* d_out, int out_size) {
    const float* images = (const float*)d_in[0];  // (16,33,256,256) f32
    const float* flows  = (const float*)d_in[1];  // (16,20,128,128) f32
    (void)in_sizes; (void)n_in; (void)out_size;

    resize_kernel<<<RES_BLOCKS, TPB>>>(images);
    smooth_kernel<<<SMOOTH_BLOCKS, TPB>>>(flows);
    warp_kernel<<<WARP_BLOCKS, TPB>>>(flows, (float*)d_out);
}

// round 12
// speedup vs baseline: 1.2656x; 1.0262x over previous
#include <cuda_runtime.h>
#include <cuda_fp16.h>
#include <math.h>

#define NB 16
#define NC 33
#define HIN 256
#define WIN 256
#define HF 128
#define WF 128
#define NFLOW 10
#define NPIX (HF * WF)                 // 16384
#define TPB 256
#define TILES 16
#define PIX_PER_BLOCK (NPIX / TILES)   // 1024
#define WARP_BLOCKS (NB * NFLOW * TILES) // 2560
#define SMOOTH_ELEMS (NB * NFLOW * HF * WF) // 2,621,440
#define SMOOTH_BLOCKS ((NB * NPIX) / TPB)  // 1024 (one thread per (b,pixel))
#define FUSED_BLOCKS (SMOOTH_BLOCKS + WARP_BLOCKS) // 3584
#define NCH (NB * NFLOW * 3)           // 480
#define RES_TOTAL (NB * NC * HF * WF)  // 8,650,752
#define RES_BLOCKS (RES_TOTAL / TPB)   // 33792

// Scratch (device globals: allocation-free)
__device__ __half g_resized[RES_TOTAL];            // ~17.3 MB (fp16)
__device__ float  g_warp_part[WARP_BLOCKS * 16];   // 3ch x 5 moments + pixel charb
__device__ float  g_smooth_part[SMOOTH_BLOCKS];
__device__ int    g_ctr;                           // zero-initialized

__device__ __forceinline__ float charb(float d) {
    // (d^2 + EPS^2)^0.4, EPS = 1e-3
    return __powf(d * d + 1.0e-6f, 0.4f);
}

// ---------------------------------------------------------------------------
// Kernel 1: align-corners bilinear resize 256x256 -> 128x128, fp16 output.
// ---------------------------------------------------------------------------
__global__ __launch_bounds__(TPB) void resize_kernel(const float* __restrict__ img) {
    int idx = blockIdx.x * TPB + threadIdx.x;
    int x  = idx & (WF - 1);
    int y  = (idx >> 7) & (HF - 1);
    int bc = idx >> 14;

    const float s = (float)(255.0 / 127.0);
    float fy = (float)y * s;
    float fx = (float)x * s;
    int y0 = min(max((int)floorf(fy), 0), HIN - 2);
    int x0 = min(max((int)floorf(fx), 0), WIN - 2);
    float wy = fy - (float)y0;
    float wx = fx - (float)x0;

    const float* p = img + (size_t)bc * (HIN * WIN);
    float v00 = __ldg(p + y0 * WIN + x0);
    float v01 = __ldg(p + y0 * WIN + x0 + 1);
    float v10 = __ldg(p + (y0 + 1) * WIN + x0);
    float v11 = __ldg(p + (y0 + 1) * WIN + x0 + 1);

    float colL = v00 * (1.0f - wy) + v10 * wy;
    float colR = v01 * (1.0f - wy) + v11 * wy;
    g_resized[idx] = __float2half_rn(colL * (1.0f - wx) + colR * wx);
}

// ---------------------------------------------------------------------------
// Kernel 2 (FUSED GRID): blocks [0, SMOOTH_BLOCKS) do smoothness (flows only,
// independent of resize); blocks [SMOOTH_BLOCKS, FUSED_BLOCKS) do the
// bilinear warp + SSIM moments + pixel charb. Smooth blocks fill warp's
// latency bubbles (warp: DRAM 21%, issue 44% -> spare capacity).
// The last block of the whole grid finalizes everything.
// ---------------------------------------------------------------------------
__global__ __launch_bounds__(TPB) void fused_kernel(const float* __restrict__ flows,
                                                    float* __restrict__ out) {
    int tid  = threadIdx.x;
    int lane = tid & 31;
    int wrp  = tid >> 5;

    __shared__ float sm[8 * 16];

    if (blockIdx.x < SMOOTH_BLOCKS) {
        // ---------------- smoothness: sliding window over flow index ----------------
        int t  = blockIdx.x * TPB + tid;
        int b  = t >> 14;
        int px = t & (NPIX - 1);
        int y  = px >> 7;
        int x  = px & (WF - 1);
        const float* fb = flows + (size_t)b * 20 * NPIX;

        float acc = 0.0f;
#pragma unroll
        for (int comp = 0; comp < 2; comp++) {
            float vp = 0.0f;
            float vc = __ldg(fb + comp * NPIX + px);         // i = 0
            float vn = __ldg(fb + (2 + comp) * NPIX + px);   // i = 1
#pragma unroll
            for (int i = 0; i < NFLOW; i++) {
                float gi = (i == 0)         ? (vn - vc)
                         : (i == NFLOW - 1) ? (vc - vp)
                                            : 0.5f * (vn - vp);
                const float* ch = fb + (2 * i + comp) * NPIX;
                float gh;
                if (y == 0)
                    gh = __ldg(ch + WF + x) - vc;
                else if (y == HF - 1)
                    gh = vc - __ldg(ch + (HF - 2) * WF + x);
                else
                    gh = 0.5f * (__ldg(ch + (y + 1) * WF + x) - __ldg(ch + (y - 1) * WF + x));

                acc += charb(gi) + charb(gh);

                vp = vc; vc = vn;
                if (i < NFLOW - 2) vn = __ldg(fb + (2 * (i + 2) + comp) * NPIX + px);
            }
        }

#pragma unroll
        for (int o = 16; o > 0; o >>= 1) acc += __shfl_down_sync(0xffffffffu, acc, o);
        if (lane == 0) sm[wrp] = acc;
        __syncthreads();
        if (tid == 0) {
            float s = 0.0f;
#pragma unroll
            for (int w = 0; w < 8; w++) s += sm[w];
            g_smooth_part[blockIdx.x] = s;
        }
    } else {
        // ---------------- warp + SSIM moments + pixel charbonnier ----------------
        int wb   = blockIdx.x - SMOOTH_BLOCKS;
        int tile = wb & (TILES - 1);
        int bf   = wb >> 4;              // TILES == 16
        int b = bf / NFLOW;
        int f = bf % NFLOW;

        const float* fxp = flows + (size_t)(b * 20 + 2 * f) * NPIX;
        const float* fyp = fxp + NPIX;
        const __half* srcbase = g_resized + (size_t)(b * NC + 3 + f * 3) * NPIX;
        const __half* refbase = g_resized + (size_t)(b * NC + f * 3) * NPIX;

        float acc[16];
#pragma unroll
        for (int i = 0; i < 16; i++) acc[i] = 0.0f;

        int p0 = tile * PIX_PER_BLOCK;
        float flx = __ldg(fxp + p0 + tid);
        float fly = __ldg(fyp + p0 + tid);
#pragma unroll
        for (int k = 0; k < PIX_PER_BLOCK; k += TPB) {
            int p = p0 + k + tid;
            float nflx = 0.0f, nfly = 0.0f;
            if (k + TPB < PIX_PER_BLOCK) {      // prefetch next iteration's flow
                nflx = __ldg(fxp + p + TPB);
                nfly = __ldg(fyp + p + TPB);
            }
            int x = p & (WF - 1);
            int y = p >> 7;

            float gx = (float)x + flx;
            float gy = (float)y + fly;
            float x0f = floorf(gx);
            float y0f = floorf(gy);
            float wx = gx - x0f;
            float wy = gy - y0f;
            int ix0 = min(max((int)x0f, 0), WF - 1);
            int iy0 = min(max((int)y0f, 0), HF - 1);
            int ix1 = min(ix0 + 1, WF - 1);
            int iy1 = min(iy0 + 1, HF - 1);

            int o00 = iy0 * WF + ix0;
            int o01 = iy0 * WF + ix1;
            int o10 = iy1 * WF + ix0;
            int o11 = iy1 * WF + ix1;

#pragma unroll
            for (int c = 0; c < 3; c++) {
                const __half* sp = srcbase + c * NPIX;
                float v00 = __half2float(__ldg(sp + o00));
                float v01 = __half2float(__ldg(sp + o01));
                float v10 = __half2float(__ldg(sp + o10));
                float v11 = __half2float(__ldg(sp + o11));
                float top = v00 * (1.0f - wx) + v01 * wx;
                float bot = v10 * (1.0f - wx) + v11 * wx;
                float w   = top * (1.0f - wy) + bot * wy;
                float r   = __half2float(__ldg(refbase + c * NPIX + p));

                acc[c * 5 + 0] += r;
                acc[c * 5 + 1] += w;
                acc[c * 5 + 2] += r * r;
                acc[c * 5 + 3] += w * w;
                acc[c * 5 + 4] += r * w;
                acc[15] += charb(r - w);
            }
            flx = nflx; fly = nfly;
        }

#pragma unroll
        for (int i = 0; i < 16; i++) {
            float v = acc[i];
#pragma unroll
            for (int o = 16; o > 0; o >>= 1) v += __shfl_down_sync(0xffffffffu, v, o);
            if (lane == 0) sm[wrp * 16 + i] = v;
        }
        __syncthreads();
        if (tid < 16) {
            float s = 0.0f;
#pragma unroll
            for (int w = 0; w < 8; w++) s += sm[w * 16 + tid];
            g_warp_part[wb * 16 + tid] = s;
        }
    }

    // ---- last-block finalization (covers BOTH populations) ----
    __shared__ bool is_last;
    __threadfence();
    __syncthreads();
    if (tid == 0) {
        int old = atomicAdd(&g_ctr, 1);
        is_last = (old == FUSED_BLOCKS - 1);
    }
    __syncthreads();
    if (!is_last) return;
    __threadfence();

    __shared__ float smom[NCH * 5];   // 2400 floats
    for (int t = tid; t < NCH * 5; t += TPB) {
        int bfc = t / 5;
        int m   = t % 5;
        int bfi = bfc / 3;
        int c   = bfc % 3;
        const float* pp = g_warp_part + (size_t)(bfi * TILES) * 16 + c * 5 + m;
        float s = 0.0f;
#pragma unroll
        for (int tl = 0; tl < TILES; tl++) s += pp[tl * 16];
        smom[t] = s;
    }

    float pix_s = 0.0f, sm_s = 0.0f;
    for (int i = tid; i < WARP_BLOCKS; i += TPB)
        pix_s += g_warp_part[i * 16 + 15];
    for (int i = tid; i < SMOOTH_BLOCKS; i += TPB)
        sm_s += g_smooth_part[i];
    __syncthreads();

    float ssim_s = 0.0f;
    for (int ch = tid; ch < NCH; ch += TPB) {
        const float* m = smom + ch * 5;
        float S1 = m[0], S2 = m[1], S11 = m[2], S22 = m[3], S12 = m[4];
        const float invN   = 1.0f / (float)NPIX;
        const float invNm1 = 1.0f / (float)(NPIX - 1);
        float mu1 = S1 * invN, mu2 = S2 * invN;
        float var1 = (S11 - S1 * S1 * invN) * invNm1;
        float var2 = (S22 - S2 * S2 * invN) * invNm1;
        float s12  = (S12 - S1 * S2 * invN) * invN;
        float num = (2.0f * mu1 * mu2 + 1.0e-4f) * (2.0f * s12 + 1.0e-3f);
        float den = (mu1 * mu1 + mu2 * mu2 + 1.0e-4f) * (var1 + var2 + 1.0e-3f);
        ssim_s += num / den;
    }

    __shared__ float sred[3 * 8];
#pragma unroll
    for (int o = 16; o > 0; o >>= 1) {
        ssim_s += __shfl_down_sync(0xffffffffu, ssim_s, o);
        pix_s  += __shfl_down_sync(0xffffffffu, pix_s,  o);
        sm_s   += __shfl_down_sync(0xffffffffu, sm_s,   o);
    }
    if (lane == 0) {
        sred[wrp * 3 + 0] = ssim_s;
        sred[wrp * 3 + 1] = pix_s;
        sred[wrp * 3 + 2] = sm_s;
    }
    __syncthreads();
    if (tid == 0) {
        float a = 0.0f, bb = 0.0f, cc = 0.0f;
#pragma unroll
        for (int w = 0; w < 8; w++) {
            a  += sred[w * 3 + 0];
            bb += sred[w * 3 + 1];
            cc += sred[w * 3 + 2];
        }
        out[0] = bb * (1.0f / (float)(NB * NFLOW * 3 * NPIX))   // pixel (w=1.0)
               + 0.01f * cc * (1.0f / (float)SMOOTH_ELEMS)      // smooth (w=0.01)
               + a * (1.0f / (float)NCH);                       // ssim (w=1.0)
        g_ctr = 0;  // reset for next graph replay
    }
}

extern "C" void kernel_launch(void* const* d_in, const int* in_sizes, int n_in,
                              void* d_out, int out_size) {
    const float* images = (const float*)d_in[0];  // (16,33,256,256) f32
    const float* flows  = (const float*)d_in[1];  // (16,20,128,128) f32
    (void)in_sizes; (void)n_in; (void)out_size;

    resize_kernel<<<RES_BLOCKS, TPB>>>(images);
    fused_kernel<<<FUSED_BLOCKS, TPB>>>(flows, (float*)d_out);
}

// round 13
// speedup vs baseline: 1.2750x; 1.0074x over previous
#include <cuda_runtime.h>
#include <cuda_fp16.h>
#include <math.h>

#define NB 16
#define NC 33
#define HIN 256
#define WIN 256
#define HF 128
#define WF 128
#define NFLOW 10
#define NPIX (HF * WF)                 // 16384
#define TPB 256
#define TILES 16
#define PIX_PER_BLOCK (NPIX / TILES)   // 1024
#define WARP_BLOCKS (NB * NFLOW * TILES) // 2560
#define SMOOTH_ELEMS (NB * NFLOW * HF * WF) // 2,621,440
#define SMOOTH_BLOCKS ((NB * NPIX) / TPB)  // 1024
#define FUSED_BLOCKS (SMOOTH_BLOCKS + WARP_BLOCKS) // 3584
#define NCH (NB * NFLOW * 3)           // 480
#define RES_TOTAL (NB * NC * HF * WF)  // 8,650,752
#define RES_BLOCKS (RES_TOTAL / (2 * TPB)) // 16896 (2 pixels per thread)

// Scratch (device globals: allocation-free)
// g_pair[idx] = (resized[x], resized[min(x+1,127)]) as half2 -> one aligned
// 4B load yields both bilinear columns.
__device__ __half2 g_pair[RES_TOTAL];              // ~34.6 MB
__device__ float   g_warp_part[WARP_BLOCKS * 16];  // 3ch x 5 moments + pixel charb
__device__ float   g_smooth_part[SMOOTH_BLOCKS];
__device__ int     g_ctr;                          // zero-initialized

__device__ __forceinline__ float charb(float d) {
    // (d^2 + EPS^2)^0.4, EPS = 1e-3
    return __powf(d * d + 1.0e-6f, 0.4f);
}

__device__ __forceinline__ float resize_interp(const float* __restrict__ p,
                                               int x, int y) {
    const float s = (float)(255.0 / 127.0);
    float fy = (float)y * s;
    float fx = (float)x * s;
    int y0 = min(max((int)floorf(fy), 0), HIN - 2);
    int x0 = min(max((int)floorf(fx), 0), WIN - 2);
    float wy = fy - (float)y0;
    float wx = fx - (float)x0;
    float v00 = __ldg(p + y0 * WIN + x0);
    float v01 = __ldg(p + y0 * WIN + x0 + 1);
    float v10 = __ldg(p + (y0 + 1) * WIN + x0);
    float v11 = __ldg(p + (y0 + 1) * WIN + x0 + 1);
    float colL = v00 * (1.0f - wy) + v10 * wy;
    float colR = v01 * (1.0f - wy) + v11 * wy;
    return colL * (1.0f - wx) + colR * wx;
}

// ---------------------------------------------------------------------------
// Kernel 1: align-corners bilinear resize 256->128, paired-half2 output.
// 2 independent pixels per thread (MLP); .y via neighbor-lane shuffle.
// ---------------------------------------------------------------------------
__global__ __launch_bounds__(TPB) void resize_kernel(const float* __restrict__ img) {
    int tid  = threadIdx.x;
    int lane = tid & 31;
    int idx0 = blockIdx.x * TPB + tid;

#pragma unroll
    for (int h = 0; h < 2; h++) {
        int idx = idx0 + h * (RES_TOTAL / 2);   // RES_TOTAL/2 divisible by NPIX
        int x  = idx & (WF - 1);
        int y  = (idx >> 7) & (HF - 1);
        int bc = idx >> 14;
        const float* p = img + (size_t)bc * (HIN * WIN);

        float v  = resize_interp(p, x, y);
        float vn = __shfl_down_sync(0xffffffffu, v, 1);
        if (lane == 31)
            vn = (x == WF - 1) ? v : resize_interp(p, x + 1, y);
        g_pair[idx] = __floats2half2_rn(v, vn);
    }
}

// ---------------------------------------------------------------------------
// Kernel 2 (FUSED GRID): smooth blocks + warp blocks; last block finalizes.
// Warp branch uses paired gathers: one half2 load per bilinear row.
// ---------------------------------------------------------------------------
__global__ __launch_bounds__(TPB) void fused_kernel(const float* __restrict__ flows,
                                                    float* __restrict__ out) {
    int tid  = threadIdx.x;
    int lane = tid & 31;
    int wrp  = tid >> 5;

    __shared__ float sm[8 * 16];

    if (blockIdx.x < SMOOTH_BLOCKS) {
        // ---------------- smoothness: sliding window over flow index ----------------
        int t  = blockIdx.x * TPB + tid;
        int b  = t >> 14;
        int px = t & (NPIX - 1);
        int y  = px >> 7;
        int x  = px & (WF - 1);
        const float* fb = flows + (size_t)b * 20 * NPIX;

        float acc = 0.0f;
#pragma unroll
        for (int comp = 0; comp < 2; comp++) {
            float vp = 0.0f;
            float vc = __ldg(fb + comp * NPIX + px);         // i = 0
            float vn = __ldg(fb + (2 + comp) * NPIX + px);   // i = 1
#pragma unroll
            for (int i = 0; i < NFLOW; i++) {
                float gi = (i == 0)         ? (vn - vc)
                         : (i == NFLOW - 1) ? (vc - vp)
                                            : 0.5f * (vn - vp);
                const float* ch = fb + (2 * i + comp) * NPIX;
                float gh;
                if (y == 0)
                    gh = __ldg(ch + WF + x) - vc;
                else if (y == HF - 1)
                    gh = vc - __ldg(ch + (HF - 2) * WF + x);
                else
                    gh = 0.5f * (__ldg(ch + (y + 1) * WF + x) - __ldg(ch + (y - 1) * WF + x));

                acc += charb(gi) + charb(gh);

                vp = vc; vc = vn;
                if (i < NFLOW - 2) vn = __ldg(fb + (2 * (i + 2) + comp) * NPIX + px);
            }
        }

#pragma unroll
        for (int o = 16; o > 0; o >>= 1) acc += __shfl_down_sync(0xffffffffu, acc, o);
        if (lane == 0) sm[wrp] = acc;
        __syncthreads();
        if (tid == 0) {
            float s = 0.0f;
#pragma unroll
            for (int w = 0; w < 8; w++) s += sm[w];
            g_smooth_part[blockIdx.x] = s;
        }
    } else {
        // ---------------- warp + SSIM moments + pixel charbonnier ----------------
        int wb   = blockIdx.x - SMOOTH_BLOCKS;
        int tile = wb & (TILES - 1);
        int bf   = wb >> 4;              // TILES == 16
        int b = bf / NFLOW;
        int f = bf % NFLOW;

        const float* fxp = flows + (size_t)(b * 20 + 2 * f) * NPIX;
        const float* fyp = fxp + NPIX;
        const __half2* srcbase = g_pair + (size_t)(b * NC + 3 + f * 3) * NPIX;
        const __half2* refbase = g_pair + (size_t)(b * NC + f * 3) * NPIX;

        float acc[16];
#pragma unroll
        for (int i = 0; i < 16; i++) acc[i] = 0.0f;

        int p0 = tile * PIX_PER_BLOCK;
        float flx = __ldg(fxp + p0 + tid);
        float fly = __ldg(fyp + p0 + tid);
#pragma unroll
        for (int k = 0; k < PIX_PER_BLOCK; k += TPB) {
            int p = p0 + k + tid;
            float nflx = 0.0f, nfly = 0.0f;
            if (k + TPB < PIX_PER_BLOCK) {      // prefetch next iteration's flow
                nflx = __ldg(fxp + p + TPB);
                nfly = __ldg(fyp + p + TPB);
            }
            int x = p & (WF - 1);
            int y = p >> 7;

            float gx = (float)x + flx;
            float gy = (float)y + fly;
            float x0f = floorf(gx);
            float y0f = floorf(gy);
            float wx = gx - x0f;
            float wy = gy - y0f;
            int ix0 = min(max((int)x0f, 0), WF - 1);
            int iy0 = min(max((int)y0f, 0), HF - 1);
            int iy1 = min(iy0 + 1, HF - 1);

            int o_top = iy0 * WF + ix0;   // pair load = (v[ix0], v[min(ix0+1,127)])
            int o_bot = iy1 * WF + ix0;

#pragma unroll
            for (int c = 0; c < 3; c++) {
                const __half2* sp = srcbase + c * NPIX;
                float2 tv = __half22float2(__ldg(sp + o_top));
                float2 bv = __half22float2(__ldg(sp + o_bot));
                float top = tv.x * (1.0f - wx) + tv.y * wx;
                float bot = bv.x * (1.0f - wx) + bv.y * wx;
                float w   = top * (1.0f - wy) + bot * wy;
                float r   = __low2float(__ldg(refbase + c * NPIX + p));

                acc[c * 5 + 0] += r;
                acc[c * 5 + 1] += w;
                acc[c * 5 + 2] += r * r;
                acc[c * 5 + 3] += w * w;
                acc[c * 5 + 4] += r * w;
                acc[15] += charb(r - w);
            }
            flx = nflx; fly = nfly;
        }

#pragma unroll
        for (int i = 0; i < 16; i++) {
            float v = acc[i];
#pragma unroll
            for (int o = 16; o > 0; o >>= 1) v += __shfl_down_sync(0xffffffffu, v, o);
            if (lane == 0) sm[wrp * 16 + i] = v;
        }
        __syncthreads();
        if (tid < 16) {
            float s = 0.0f;
#pragma unroll
            for (int w = 0; w < 8; w++) s += sm[w * 16 + tid];
            g_warp_part[wb * 16 + tid] = s;
        }
    }

    // ---- last-block finalization (covers BOTH populations) ----
    __shared__ bool is_last;
    __threadfence();
    __syncthreads();
    if (tid == 0) {
        int old = atomicAdd(&g_ctr, 1);
        is_last = (old == FUSED_BLOCKS - 1);
    }
    __syncthreads();
    if (!is_last) return;
    __threadfence();

    __shared__ float smom[NCH * 5];   // 2400 floats
    for (int t = tid; t < NCH * 5; t += TPB) {
        int bfc = t / 5;
        int m   = t % 5;
        int bfi = bfc / 3;
        int c   = bfc % 3;
        const float* pp = g_warp_part + (size_t)(bfi * TILES) * 16 + c * 5 + m;
        float s = 0.0f;
#pragma unroll
        for (int tl = 0; tl < TILES; tl++) s += pp[tl * 16];
        smom[t] = s;
    }

    float pix_s = 0.0f, sm_s = 0.0f;
    for (int i = tid; i < WARP_BLOCKS; i += TPB)
        pix_s += g_warp_part[i * 16 + 15];
    for (int i = tid; i < SMOOTH_BLOCKS; i += TPB)
        sm_s += g_smooth_part[i];
    __syncthreads();

    float ssim_s = 0.0f;
    for (int ch = tid; ch < NCH; ch += TPB) {
        const float* m = smom + ch * 5;
        float S1 = m[0], S2 = m[1], S11 = m[2], S22 = m[3], S12 = m[4];
        const float invN   = 1.0f / (float)NPIX;
        const float invNm1 = 1.0f / (float)(NPIX - 1);
        float mu1 = S1 * invN, mu2 = S2 * invN;
        float var1 = (S11 - S1 * S1 * invN) * invNm1;
        float var2 = (S22 - S2 * S2 * invN) * invNm1;
        float s12  = (S12 - S1 * S2 * invN) * invN;
        float num = (2.0f * mu1 * mu2 + 1.0e-4f) * (2.0f * s12 + 1.0e-3f);
        float den = (mu1 * mu1 + mu2 * mu2 + 1.0e-4f) * (var1 + var2 + 1.0e-3f);
        ssim_s += num / den;
    }

    __shared__ float sred[3 * 8];
#pragma unroll
    for (int o = 16; o > 0; o >>= 1) {
        ssim_s += __shfl_down_sync(0xffffffffu, ssim_s, o);
        pix_s  += __shfl_down_sync(0xffffffffu, pix_s,  o);
        sm_s   += __shfl_down_sync(0xffffffffu, sm_s,   o);
    }
    if (lane == 0) {
        sred[wrp * 3 + 0] = ssim_s;
        sred[wrp * 3 + 1] = pix_s;
        sred[wrp * 3 + 2] = sm_s;
    }
    __syncthreads();
    if (tid == 0) {
        float a = 0.0f, bb = 0.0f, cc = 0.0f;
#pragma unroll
        for (int w = 0; w < 8; w++) {
            a  += sred[w * 3 + 0];
            bb += sred[w * 3 + 1];
            cc += sred[w * 3 + 2];
        }
        out[0] = bb * (1.0f / (float)(NB * NFLOW * 3 * NPIX))   // pixel (w=1.0)
               + 0.01f * cc * (1.0f / (float)SMOOTH_ELEMS)      // smooth (w=0.01)
               + a * (1.0f / (float)NCH);                       // ssim (w=1.0)
        g_ctr = 0;  // reset for next graph replay
    }
}

extern "C" void kernel_launch(void* const* d_in, const int* in_sizes, int n_in,
                              void* d_out, int out_size) {
    const float* images = (const float*)d_in[0];  // (16,33,256,256) f32
    const float* flows  = (const float*)d_in[1];  // (16,20,128,128) f32
    (void)in_sizes; (void)n_in; (void)out_size;

    resize_kernel<<<RES_BLOCKS, TPB>>>(images);
    fused_kernel<<<FUSED_BLOCKS, TPB>>>(flows, (float*)d_out);
}

// round 15
// speedup vs baseline: 1.4657x; 1.1496x over previous
#include <cuda_runtime.h>
#include <cuda_fp16.h>
#include <math.h>

#define NB 16
#define NC 33
#define HIN 256
#define WIN 256
#define HF 128
#define WF 128
#define NFLOW 10
#define NPIX (HF * WF)                 // 16384
#define TPB 256
#define TILES 16
#define PIX_PER_BLOCK (NPIX / TILES)   // 1024
#define WARP_BLOCKS (NB * NFLOW * TILES) // 2560
#define SMOOTH_ELEMS (NB * NFLOW * HF * WF) // 2,621,440
#define SMOOTH_BLOCKS ((NB * NPIX) / TPB)  // 1024
#define NCH (NB * NFLOW * 3)           // 480
#define RES_TOTAL (NB * NC * HF * WF)  // 8,650,752
#define RES_BLOCKS (RES_TOTAL / (2 * TPB)) // 16896 (2 pixels per thread)
#define KA_BLOCKS (SMOOTH_BLOCKS + RES_BLOCKS) // 17920

// Scratch (device globals: allocation-free)
// g_pair[idx] = (resized[x], resized[min(x+1,127)]) as half2 -> one aligned
// 4B load yields both bilinear columns.
__device__ __half2 g_pair[RES_TOTAL];              // ~34.6 MB
__device__ float   g_warp_part[WARP_BLOCKS * 16];  // 3ch x 5 moments + pixel charb
__device__ float   g_smooth_part[SMOOTH_BLOCKS];
__device__ int     g_ctr;                          // zero-initialized

__device__ __forceinline__ float charb(float d) {
    // (d^2 + EPS^2)^0.4, EPS = 1e-3
    return __powf(d * d + 1.0e-6f, 0.4f);
}

__device__ __forceinline__ float resize_interp(const float* __restrict__ p,
                                               int x, int y) {
    const float s = (float)(255.0 / 127.0);
    float fy = (float)y * s;
    float fx = (float)x * s;
    int y0 = min(max((int)floorf(fy), 0), HIN - 2);
    int x0 = min(max((int)floorf(fx), 0), WIN - 2);
    float wy = fy - (float)y0;
    float wx = fx - (float)x0;
    float v00 = __ldg(p + y0 * WIN + x0);
    float v01 = __ldg(p + y0 * WIN + x0 + 1);
    float v10 = __ldg(p + (y0 + 1) * WIN + x0);
    float v11 = __ldg(p + (y0 + 1) * WIN + x0 + 1);
    float colL = v00 * (1.0f - wy) + v10 * wy;
    float colR = v01 * (1.0f - wy) + v11 * wy;
    return colL * (1.0f - wx) + colR * wx;
}

// ---------------------------------------------------------------------------
// Kernel A (heterogeneous grid): blocks [0, SMOOTH_BLOCKS) run the smoothness
// term (flows only — independent of resize, MUFU/L2-bound); the remaining
// blocks run the DRAM-bound resize. The two populations overlap (R5 evidence:
// ~8us saved with the slower smooth).
// ---------------------------------------------------------------------------
__global__ __launch_bounds__(TPB) void resize_smooth_kernel(
        const float* __restrict__ img, const float* __restrict__ flows) {
    int tid  = threadIdx.x;
    int lane = tid & 31;

    if (blockIdx.x < SMOOTH_BLOCKS) {
        // ---------------- smoothness: sliding window over flow index ----------------
        int t  = blockIdx.x * TPB + tid;
        int b  = t >> 14;
        int px = t & (NPIX - 1);
        int y  = px >> 7;
        int x  = px & (WF - 1);
        const float* fb = flows + (size_t)b * 20 * NPIX;

        float acc = 0.0f;
#pragma unroll
        for (int comp = 0; comp < 2; comp++) {
            float vp = 0.0f;
            float vc = __ldg(fb + comp * NPIX + px);         // i = 0
            float vn = __ldg(fb + (2 + comp) * NPIX + px);   // i = 1
#pragma unroll
            for (int i = 0; i < NFLOW; i++) {
                float gi = (i == 0)         ? (vn - vc)
                         : (i == NFLOW - 1) ? (vc - vp)
                                            : 0.5f * (vn - vp);
                const float* ch = fb + (2 * i + comp) * NPIX;
                float gh;
                if (y == 0)
                    gh = __ldg(ch + WF + x) - vc;
                else if (y == HF - 1)
                    gh = vc - __ldg(ch + (HF - 2) * WF + x);
                else
                    gh = 0.5f * (__ldg(ch + (y + 1) * WF + x) - __ldg(ch + (y - 1) * WF + x));

                acc += charb(gi) + charb(gh);

                vp = vc; vc = vn;
                if (i < NFLOW - 2) vn = __ldg(fb + (2 * (i + 2) + comp) * NPIX + px);
            }
        }

        __shared__ float sm[8];
        int wrp = tid >> 5;
#pragma unroll
        for (int o = 16; o > 0; o >>= 1) acc += __shfl_down_sync(0xffffffffu, acc, o);
        if (lane == 0) sm[wrp] = acc;
        __syncthreads();
        if (tid == 0) {
            float s = 0.0f;
#pragma unroll
            for (int w = 0; w < 8; w++) s += sm[w];
            g_smooth_part[blockIdx.x] = s;
        }
    } else {
        // ---------------- resize: 2 independent pixels/thread, pair output ----------------
        int idx0 = (blockIdx.x - SMOOTH_BLOCKS) * TPB + tid;
#pragma unroll
        for (int h = 0; h < 2; h++) {
            int idx = idx0 + h * (RES_TOTAL / 2);   // RES_TOTAL/2 divisible by NPIX
            int x  = idx & (WF - 1);
            int y  = (idx >> 7) & (HF - 1);
            int bc = idx >> 14;
            const float* p = img + (size_t)bc * (HIN * WIN);

            float v  = resize_interp(p, x, y);
            float vn = __shfl_down_sync(0xffffffffu, v, 1);
            if (lane == 31)
                vn = (x == WF - 1) ? v : resize_interp(p, x + 1, y);
            g_pair[idx] = __floats2half2_rn(v, vn);
        }
    }
}

// ---------------------------------------------------------------------------
// Kernel B: bilinear warp + SSIM moments + pixel charbonnier, paired gathers;
// last block finalizes everything (smooth partials came from kernel A).
// ---------------------------------------------------------------------------
__global__ __launch_bounds__(TPB) void warp_kernel(const float* __restrict__ flows,
                                                   float* __restrict__ out) {
    int tid  = threadIdx.x;
    int lane = tid & 31;
    int wrp  = tid >> 5;

    __shared__ float sm[8 * 16];

    int wb   = blockIdx.x;
    int tile = wb & (TILES - 1);
    int bf   = wb >> 4;              // TILES == 16
    int b = bf / NFLOW;
    int f = bf % NFLOW;

    const float* fxp = flows + (size_t)(b * 20 + 2 * f) * NPIX;
    const float* fyp = fxp + NPIX;
    const __half2* srcbase = g_pair + (size_t)(b * NC + 3 + f * 3) * NPIX;
    const __half2* refbase = g_pair + (size_t)(b * NC + f * 3) * NPIX;

    float acc[16];
#pragma unroll
    for (int i = 0; i < 16; i++) acc[i] = 0.0f;

    int p0 = tile * PIX_PER_BLOCK;
    float flx = __ldg(fxp + p0 + tid);
    float fly = __ldg(fyp + p0 + tid);
#pragma unroll
    for (int k = 0; k < PIX_PER_BLOCK; k += TPB) {
        int p = p0 + k + tid;
        float nflx = 0.0f, nfly = 0.0f;
        if (k + TPB < PIX_PER_BLOCK) {      // prefetch next iteration's flow
            nflx = __ldg(fxp + p + TPB);
            nfly = __ldg(fyp + p + TPB);
        }
        int x = p & (WF - 1);
        int y = p >> 7;

        float gx = (float)x + flx;
        float gy = (float)y + fly;
        float x0f = floorf(gx);
        float y0f = floorf(gy);
        float wx = gx - x0f;
        float wy = gy - y0f;
        int ix0 = min(max((int)x0f, 0), WF - 1);
        int iy0 = min(max((int)y0f, 0), HF - 1);
        int iy1 = min(iy0 + 1, HF - 1);

        int o_top = iy0 * WF + ix0;   // pair load = (v[ix0], v[min(ix0+1,127)])
        int o_bot = iy1 * WF + ix0;

#pragma unroll
        for (int c = 0; c < 3; c++) {
            const __half2* sp = srcbase + c * NPIX;
            float2 tv = __half22float2(__ldg(sp + o_top));
            float2 bv = __half22float2(__ldg(sp + o_bot));
            float top = tv.x * (1.0f - wx) + tv.y * wx;
            float bot = bv.x * (1.0f - wx) + bv.y * wx;
            float w   = top * (1.0f - wy) + bot * wy;
            float r   = __low2float(__ldg(refbase + c * NPIX + p));

            acc[c * 5 + 0] += r;
            acc[c * 5 + 1] += w;
            acc[c * 5 + 2] += r * r;
            acc[c * 5 + 3] += w * w;
            acc[c * 5 + 4] += r * w;
            acc[15] += charb(r - w);
        }
        flx = nflx; fly = nfly;
    }

#pragma unroll
    for (int i = 0; i < 16; i++) {
        float v = acc[i];
#pragma unroll
        for (int o = 16; o > 0; o >>= 1) v += __shfl_down_sync(0xffffffffu, v, o);
        if (lane == 0) sm[wrp * 16 + i] = v;
    }
    __syncthreads();
    if (tid < 16) {
        float s = 0.0f;
#pragma unroll
        for (int w = 0; w < 8; w++) s += sm[w * 16 + tid];
        g_warp_part[wb * 16 + tid] = s;
    }

    // ---- last-block finalization ----
    __shared__ bool is_last;
    __threadfence();
    __syncthreads();
    if (tid == 0) {
        int old = atomicAdd(&g_ctr, 1);
        is_last = (old == WARP_BLOCKS - 1);
    }
    __syncthreads();
    if (!is_last) return;
    __threadfence();

    __shared__ float smom[NCH * 5];   // 2400 floats
    for (int t = tid; t < NCH * 5; t += TPB) {
        int bfc = t / 5;
        int m   = t % 5;
        int bfi = bfc / 3;
        int c   = bfc % 3;
        const float* pp = g_warp_part + (size_t)(bfi * TILES) * 16 + c * 5 + m;
        float s = 0.0f;
#pragma unroll
        for (int tl = 0; tl < TILES; tl++) s += pp[tl * 16];
        smom[t] = s;
    }

    float pix_s = 0.0f, sm_s = 0.0f;
    for (int i = tid; i < WARP_BLOCKS; i += TPB)
        pix_s += g_warp_part[i * 16 + 15];
    for (int i = tid; i < SMOOTH_BLOCKS; i += TPB)
        sm_s += g_smooth_part[i];
    __syncthreads();

    float ssim_s = 0.0f;
    for (int ch = tid; ch < NCH; ch += TPB) {
        const float* m = smom + ch * 5;
        float S1 = m[0], S2 = m[1], S11 = m[2], S22 = m[3], S12 = m[4];
        const float invN   = 1.0f / (float)NPIX;
        const float invNm1 = 1.0f / (float)(NPIX - 1);
        float mu1 = S1 * invN, mu2 = S2 * invN;
        float var1 = (S11 - S1 * S1 * invN) * invNm1;
        float var2 = (S22 - S2 * S2 * invN) * invNm1;
        float s12  = (S12 - S1 * S2 * invN) * invN;
        float num = (2.0f * mu1 * mu2 + 1.0e-4f) * (2.0f * s12 + 1.0e-3f);
        float den = (mu1 * mu1 + mu2 * mu2 + 1.0e-4f) * (var1 + var2 + 1.0e-3f);
        ssim_s += num / den;
    }

    __shared__ float sred[3 * 8];
#pragma unroll
    for (int o = 16; o > 0; o >>= 1) {
        ssim_s += __shfl_down_sync(0xffffffffu, ssim_s, o);
        pix_s  += __shfl_down_sync(0xffffffffu, pix_s,  o);
        sm_s   += __shfl_down_sync(0xffffffffu, sm_s,   o);
    }
    if (lane == 0) {
        sred[wrp * 3 + 0] = ssim_s;
        sred[wrp * 3 + 1] = pix_s;
        sred[wrp * 3 + 2] = sm_s;
    }
    __syncthreads();
    if (tid == 0) {
        float a = 0.0f, bb = 0.0f, cc = 0.0f;
#pragma unroll
        for (int w = 0; w < 8; w++) {
            a  += sred[w * 3 + 0];
            bb += sred[w * 3 + 1];
            cc += sred[w * 3 + 2];
        }
        out[0] = bb * (1.0f / (float)(NB * NFLOW * 3 * NPIX))   // pixel (w=1.0)
               + 0.01f * cc * (1.0f / (float)SMOOTH_ELEMS)      // smooth (w=0.01)
               + a * (1.0f / (float)NCH);                       // ssim (w=1.0)
        g_ctr = 0;  // reset for next graph replay
    }
}

extern "C" void kernel_launch(void* const* d_in, const int* in_sizes, int n_in,
                              void* d_out, int out_size) {
    const float* images = (const float*)d_in[0];  // (16,33,256,256) f32
    const float* flows  = (const float*)d_in[1];  // (16,20,128,128) f32
    (void)in_sizes; (void)n_in; (void)out_size;

    resize_smooth_kernel<<<KA_BLOCKS, TPB>>>(images, flows);
    warp_kernel<<<WARP_BLOCKS, TPB>>>(flows, (float*)d_out);
}